// round 1
// baseline (speedup 1.0000x reference)
#include <cuda_runtime.h>
#include <math.h>

// Problem constants
#define BB 512
#define TT 2048
#define II 32
#define NH1 30
#define NH2 15
#define NFC 16
#define NNC 10

static const long MROWS = (long)BB * TT;  // 1,048,576

// Scratch (static device globals; no allocation allowed)
__device__ float g_gx[(size_t)BB * TT * 90];    // max 3H = 90
__device__ float g_bufA[(size_t)BB * TT * 30];  // layer outputs H<=30
__device__ float g_bufB[(size_t)BB * TT * 16];  // layer outputs H<=16 (also holds H=15)

__device__ __forceinline__ float sigmoidf_(float x) {
    return 1.0f / (1.0f + expf(-x));
}

// ---------------------------------------------------------------------------
// gx kernel: out[row, g] = b[g] + sum_k in[row, k] * w[g, k]
// rows = B*T, IN = input dim, G3 = 3*H
// ---------------------------------------------------------------------------
template <int IN, int G3>
__global__ void __launch_bounds__(256) gx_kernel(const float* __restrict__ x,
                                                 const float* __restrict__ w,
                                                 const float* __restrict__ b,
                                                 float* __restrict__ out) {
    constexpr int ROWS = 32;
    constexpr int INP = IN | 1;  // odd pad -> conflict-free
    __shared__ float sw[G3 * INP];
    __shared__ float sb[G3];
    __shared__ float sx[ROWS * INP];

    const int tid = threadIdx.x;
    const long row0 = (long)blockIdx.x * ROWS;

    for (int i = tid; i < G3 * IN; i += 256) {
        int g = i / IN, k = i - g * IN;
        sw[g * INP + k] = w[i];
    }
    for (int i = tid; i < G3; i += 256) sb[i] = b[i];
    for (int i = tid; i < ROWS * IN; i += 256) {
        int r = i / IN, k = i - r * IN;
        sx[r * INP + k] = x[row0 * IN + i];
    }
    __syncthreads();

    for (int o = tid; o < ROWS * G3; o += 256) {
        int r = o / G3, g = o - r * G3;
        float a = sb[g];
#pragma unroll
        for (int k = 0; k < IN; k++)
            a = fmaf(sx[r * INP + k], sw[g * INP + k], a);
        out[row0 * G3 + o] = a;
    }
}

// ---------------------------------------------------------------------------
// Sequential GRU recurrence per layer. One block per batch element.
// gx: [B, T, 3H] precomputed input gates (with b_ih). out: [B, T, H].
// ---------------------------------------------------------------------------
template <int H>
__global__ void seq_kernel(const float* __restrict__ gx,
                           const float* __restrict__ w_hh,
                           const float* __restrict__ b_hh,
                           float* __restrict__ out) {
    constexpr int G3 = 3 * H;
    const int b = blockIdx.x;
    const int g = threadIdx.x;

    __shared__ float sh_h[H];
    __shared__ float sh_r[H];
    __shared__ float sh_z[H];

    float wrow[H];
    float bb = 0.0f;
    if (g < G3) {
        bb = b_hh[g];
#pragma unroll
        for (int k = 0; k < H; k++) wrow[k] = w_hh[g * H + k];
    }
    if (g < H) sh_h[g] = 0.0f;
    __syncthreads();

    const float* __restrict__ gxp = gx + (size_t)b * TT * G3;
    float* __restrict__ op = out + (size_t)b * TT * H;

    for (int t = 0; t < TT; t++) {
        float gxv = 0.0f, acc = 0.0f;
        if (g < G3) {
            gxv = gxp[(size_t)t * G3 + g];  // issued early, hidden behind dot
            float a0 = bb, a1 = 0.0f;
#pragma unroll
            for (int k = 0; k + 1 < H; k += 2) {
                a0 = fmaf(sh_h[k], wrow[k], a0);
                a1 = fmaf(sh_h[k + 1], wrow[k + 1], a1);
            }
            if (H & 1) a0 = fmaf(sh_h[H - 1], wrow[H - 1], a0);
            acc = a0 + a1;
        }
        if (g < H) {
            sh_r[g] = sigmoidf_(gxv + acc);
        } else if (g < 2 * H) {
            sh_z[g - H] = sigmoidf_(gxv + acc);
        }
        __syncthreads();
        if (g >= 2 * H && g < G3) {
            int j = g - 2 * H;
            float n = tanhf(gxv + sh_r[j] * acc);
            float hnew = n + sh_z[j] * (sh_h[j] - n);
            sh_h[j] = hnew;
            op[(size_t)t * H + j] = hnew;
        }
        __syncthreads();
    }
}

// ---------------------------------------------------------------------------
// FC + transpose: out[b, c, t] = fc_b[c] + sum_k h4[b, t, k] * fc_w[c, k]
// ---------------------------------------------------------------------------
__global__ void __launch_bounds__(256) fc_kernel(const float* __restrict__ h4,
                                                 const float* __restrict__ fcw,
                                                 const float* __restrict__ fcb,
                                                 float* __restrict__ out) {
    constexpr int RT = 128;  // t-rows per block
    __shared__ float sh[RT * 17];
    __shared__ float sfw[NNC * NFC];
    __shared__ float sfb[NNC];

    const int tid = threadIdx.x;
    const int b = blockIdx.y;
    const int t0 = blockIdx.x * RT;

    if (tid < NNC * NFC) sfw[tid] = fcw[tid];
    if (tid < NNC) sfb[tid] = fcb[tid];

    const float* __restrict__ in = h4 + ((size_t)b * TT + t0) * NFC;
    for (int i = tid; i < RT * NFC; i += 256) {
        int r = i >> 4, k = i & 15;
        sh[r * 17 + k] = in[i];
    }
    __syncthreads();

    for (int o = tid; o < NNC * RT; o += 256) {
        int c = o >> 7;       // /128
        int trow = o & 127;   // %128
        float a = sfb[c];
#pragma unroll
        for (int k = 0; k < NFC; k++)
            a = fmaf(sh[trow * 17 + k], sfw[c * NFC + k], a);
        out[((size_t)b * NNC + c) * TT + t0 + trow] = a;
    }
}

// ---------------------------------------------------------------------------
extern "C" void kernel_launch(void* const* d_in, const int* in_sizes, int n_in,
                              void* d_out, int out_size) {
    const float* x    = (const float*)d_in[0];
    const float* fcw  = (const float*)d_in[1];
    const float* fcb  = (const float*)d_in[2];
    const float* wih1 = (const float*)d_in[3];
    const float* whh1 = (const float*)d_in[4];
    const float* bih1 = (const float*)d_in[5];
    const float* bhh1 = (const float*)d_in[6];
    const float* wih2 = (const float*)d_in[7];
    const float* whh2 = (const float*)d_in[8];
    const float* bih2 = (const float*)d_in[9];
    const float* bhh2 = (const float*)d_in[10];
    const float* wih3 = (const float*)d_in[11];
    const float* whh3 = (const float*)d_in[12];
    const float* bih3 = (const float*)d_in[13];
    const float* bhh3 = (const float*)d_in[14];
    const float* wih4 = (const float*)d_in[15];
    const float* whh4 = (const float*)d_in[16];
    const float* bih4 = (const float*)d_in[17];
    const float* bhh4 = (const float*)d_in[18];
    float* out = (float*)d_out;

    float *gx, *bufA, *bufB;
    cudaGetSymbolAddress((void**)&gx, g_gx);
    cudaGetSymbolAddress((void**)&bufA, g_bufA);
    cudaGetSymbolAddress((void**)&bufB, g_bufB);

    const int gxGrid = (int)(MROWS / 32);  // 32768

    // Layer 1: in=32, H=30
    gx_kernel<32, 90><<<gxGrid, 256>>>(x, wih1, bih1, gx);
    seq_kernel<30><<<BB, 96>>>(gx, whh1, bhh1, bufA);
    // Layer 2: in=30, H=15
    gx_kernel<30, 45><<<gxGrid, 256>>>(bufA, wih2, bih2, gx);
    seq_kernel<15><<<BB, 64>>>(gx, whh2, bhh2, bufB);
    // Layer 3: in=15, H=30
    gx_kernel<15, 90><<<gxGrid, 256>>>(bufB, wih3, bih3, gx);
    seq_kernel<30><<<BB, 96>>>(gx, whh3, bhh3, bufA);
    // Layer 4: in=30, H=16
    gx_kernel<30, 48><<<gxGrid, 256>>>(bufA, wih4, bih4, gx);
    seq_kernel<16><<<BB, 64>>>(gx, whh4, bhh4, bufB);
    // FC + transpose
    dim3 fcGrid(TT / 128, BB);
    fc_kernel<<<fcGrid, 256>>>(bufB, fcw, fcb, out);
}

// round 2
// speedup vs baseline: 1.3104x; 1.3104x over previous
#include <cuda_runtime.h>
#include <math.h>

#define BB 512
#define TT 2048

// Scratch (static device globals). g_gx padded for the prefetch ring overrun.
__device__ float g_gx[(size_t)BB * TT * 90 + 8192];
__device__ float g_bufA[(size_t)BB * TT * 30];
__device__ float g_bufB[(size_t)BB * TT * 16];

__device__ __forceinline__ float fsig(float x) {
    return __fdividef(1.0f, 1.0f + __expf(-x));
}
__device__ __forceinline__ float ftanh_(float x) {
    return 1.0f - __fdividef(2.0f, __expf(2.0f * x) + 1.0f);
}

// ---------------------------------------------------------------------------
// gx kernel v2: out[row, g] = b[g] + sum_k in[row, k] * w[g, k]
// Register tile: 4 gates per thread, float4 over k. 64 rows per block.
// ---------------------------------------------------------------------------
template <int IN, int G3>
__global__ void __launch_bounds__(256) gx_kernel(const float* __restrict__ x,
                                                 const float* __restrict__ w,
                                                 const float* __restrict__ b,
                                                 float* __restrict__ out) {
    constexpr int ROWS = 64;
    constexpr int KP  = (((IN + 3) & ~3) + 4);   // padded k stride (odd # of float4)
    constexpr int KU  = (IN + 3) / 4;            // float4 chunks holding real data
    constexpr int G3p = (G3 + 3) & ~3;           // gates padded to multiple of 4
    constexpr int GQ  = G3p / 4;

    __shared__ float sw[G3p * KP];
    __shared__ float sx[ROWS * KP];
    __shared__ float sb[G3p];

    const int tid = threadIdx.x;
    const long row0 = (long)blockIdx.x * ROWS;

    // zero-fill (covers padding), then fill real data
    for (int i = tid; i < G3p * KP; i += 256) sw[i] = 0.0f;
    for (int i = tid; i < ROWS * KP; i += 256) sx[i] = 0.0f;
    __syncthreads();
    for (int i = tid; i < G3 * IN; i += 256) {
        int g = i / IN, k = i - g * IN;
        sw[g * KP + k] = w[i];
    }
    for (int i = tid; i < G3p; i += 256) sb[i] = (i < G3) ? b[i] : 0.0f;
    for (int i = tid; i < ROWS * IN; i += 256) {
        int r = i / IN, k = i - r * IN;
        sx[r * KP + k] = x[row0 * IN + i];
    }
    __syncthreads();

    const float4* sw4 = reinterpret_cast<const float4*>(sw);
    const float4* sx4 = reinterpret_cast<const float4*>(sx);
    constexpr int KP4 = KP / 4;

    for (int idx = tid; idx < ROWS * GQ; idx += 256) {
        int r  = idx / GQ;
        int gq = idx - r * GQ;
        int g0 = gq * 4;
        float a0 = sb[g0], a1 = sb[g0 + 1], a2 = sb[g0 + 2], a3 = sb[g0 + 3];
#pragma unroll
        for (int k4 = 0; k4 < KU; k4++) {
            float4 xv = sx4[r * KP4 + k4];
            float4 w0 = sw4[(g0 + 0) * KP4 + k4];
            float4 w1 = sw4[(g0 + 1) * KP4 + k4];
            float4 w2 = sw4[(g0 + 2) * KP4 + k4];
            float4 w3 = sw4[(g0 + 3) * KP4 + k4];
            a0 = fmaf(xv.x, w0.x, fmaf(xv.y, w0.y, fmaf(xv.z, w0.z, fmaf(xv.w, w0.w, a0))));
            a1 = fmaf(xv.x, w1.x, fmaf(xv.y, w1.y, fmaf(xv.z, w1.z, fmaf(xv.w, w1.w, a1))));
            a2 = fmaf(xv.x, w2.x, fmaf(xv.y, w2.y, fmaf(xv.z, w2.z, fmaf(xv.w, w2.w, a2))));
            a3 = fmaf(xv.x, w3.x, fmaf(xv.y, w3.y, fmaf(xv.z, w3.z, fmaf(xv.w, w3.w, a3))));
        }
        float* op = out + (row0 + r) * G3;
        if (g0 + 0 < G3) op[g0 + 0] = a0;
        if (g0 + 1 < G3) op[g0 + 1] = a1;
        if (g0 + 2 < G3) op[g0 + 2] = a2;
        if (g0 + 3 < G3) op[g0 + 3] = a3;
    }
}

// ---------------------------------------------------------------------------
// Warp-per-batch GRU recurrence. Lane j owns hidden unit j (all 3 gates).
// h broadcast via shuffles; gx prefetched 4 steps ahead in a register ring.
// No shared memory, no __syncthreads.
// ---------------------------------------------------------------------------
template <int H>
__global__ void __launch_bounds__(32) seq_warp(const float* __restrict__ gx,
                                               const float* __restrict__ w_hh,
                                               const float* __restrict__ b_hh,
                                               float* __restrict__ out) {
    constexpr int G3 = 3 * H;
    const int b = blockIdx.x;
    const int j = threadIdx.x;
    const bool act = (j < H);

    float wr[H], wz[H], wn[H];
    float br = 0.f, bz = 0.f, bn = 0.f, h = 0.f;
#pragma unroll
    for (int k = 0; k < H; k++) {
        wr[k] = act ? w_hh[(0 * H + j) * H + k] : 0.f;
        wz[k] = act ? w_hh[(1 * H + j) * H + k] : 0.f;
        wn[k] = act ? w_hh[(2 * H + j) * H + k] : 0.f;
    }
    if (act) { br = b_hh[j]; bz = b_hh[H + j]; bn = b_hh[2 * H + j]; }

    const float* __restrict__ gp = gx + (size_t)b * TT * G3;
    float* __restrict__ op = out + (size_t)b * TT * H;

    // prefetch ring, depth 4
    float pr[4], pz[4], pn[4];
#pragma unroll
    for (int s = 0; s < 4; s++) {
        pr[s] = act ? gp[(size_t)s * G3 + j] : 0.f;
        pz[s] = act ? gp[(size_t)s * G3 + H + j] : 0.f;
        pn[s] = act ? gp[(size_t)s * G3 + 2 * H + j] : 0.f;
    }

    for (int t = 0; t < TT; t += 4) {
#pragma unroll
        for (int u = 0; u < 4; u++) {
            float xr = pr[u], xz = pz[u], xn = pn[u];
            // prefetch t+4+u (pad on g_gx covers tail overrun)
            {
                size_t off = (size_t)(t + 4 + u) * G3;
                pr[u] = act ? gp[off + j] : 0.f;
                pz[u] = act ? gp[off + H + j] : 0.f;
                pn[u] = act ? gp[off + 2 * H + j] : 0.f;
            }
            float ar0 = br, ar1 = 0.f, az0 = bz, az1 = 0.f, an0 = bn, an1 = 0.f;
#pragma unroll
            for (int k = 0; k < H; k++) {
                float hk = __shfl_sync(0xffffffffu, h, k);
                if (k & 1) {
                    ar1 = fmaf(hk, wr[k], ar1);
                    az1 = fmaf(hk, wz[k], az1);
                    an1 = fmaf(hk, wn[k], an1);
                } else {
                    ar0 = fmaf(hk, wr[k], ar0);
                    az0 = fmaf(hk, wz[k], az0);
                    an0 = fmaf(hk, wn[k], an0);
                }
            }
            float dr = ar0 + ar1, dz = az0 + az1, dn = an0 + an1;
            float r = fsig(xr + dr);
            float z = fsig(xz + dz);
            float n = ftanh_(fmaf(r, dn, xn));
            h = fmaf(z, h - n, n);
            if (act) op[(size_t)(t + u) * H + j] = h;
        }
    }
}

// ---------------------------------------------------------------------------
// FC + transpose: out[b, c, t] = fc_b[c] + sum_k h4[b, t, k] * fc_w[c, k]
// ---------------------------------------------------------------------------
__global__ void __launch_bounds__(256) fc_kernel(const float* __restrict__ h4,
                                                 const float* __restrict__ fcw,
                                                 const float* __restrict__ fcb,
                                                 float* __restrict__ out) {
    constexpr int RT = 128;
    constexpr int NFC = 16, NNC = 10;
    __shared__ float sh[RT * 17];
    __shared__ float sfw[NNC * NFC];
    __shared__ float sfb[NNC];

    const int tid = threadIdx.x;
    const int b = blockIdx.y;
    const int t0 = blockIdx.x * RT;

    if (tid < NNC * NFC) sfw[tid] = fcw[tid];
    if (tid < NNC) sfb[tid] = fcb[tid];

    const float* __restrict__ in = h4 + ((size_t)b * TT + t0) * NFC;
    for (int i = tid; i < RT * NFC; i += 256) {
        int r = i >> 4, k = i & 15;
        sh[r * 17 + k] = in[i];
    }
    __syncthreads();

    for (int o = tid; o < NNC * RT; o += 256) {
        int c = o >> 7;
        int trow = o & 127;
        float a = sfb[c];
#pragma unroll
        for (int k = 0; k < NFC; k++)
            a = fmaf(sh[trow * 17 + k], sfw[c * NFC + k], a);
        out[((size_t)b * NNC + c) * TT + t0 + trow] = a;
    }
}

// ---------------------------------------------------------------------------
extern "C" void kernel_launch(void* const* d_in, const int* in_sizes, int n_in,
                              void* d_out, int out_size) {
    const float* x    = (const float*)d_in[0];
    const float* fcw  = (const float*)d_in[1];
    const float* fcb  = (const float*)d_in[2];
    const float* wih1 = (const float*)d_in[3];
    const float* whh1 = (const float*)d_in[4];
    const float* bih1 = (const float*)d_in[5];
    const float* bhh1 = (const float*)d_in[6];
    const float* wih2 = (const float*)d_in[7];
    const float* whh2 = (const float*)d_in[8];
    const float* bih2 = (const float*)d_in[9];
    const float* bhh2 = (const float*)d_in[10];
    const float* wih3 = (const float*)d_in[11];
    const float* whh3 = (const float*)d_in[12];
    const float* bih3 = (const float*)d_in[13];
    const float* bhh3 = (const float*)d_in[14];
    const float* wih4 = (const float*)d_in[15];
    const float* whh4 = (const float*)d_in[16];
    const float* bih4 = (const float*)d_in[17];
    const float* bhh4 = (const float*)d_in[18];
    float* out = (float*)d_out;

    float *gx, *bufA, *bufB;
    cudaGetSymbolAddress((void**)&gx, g_gx);
    cudaGetSymbolAddress((void**)&bufA, g_bufA);
    cudaGetSymbolAddress((void**)&bufB, g_bufB);

    const int gxGrid = (int)(((long)BB * TT) / 64);  // 16384

    // Layer 1: in=32, H=30
    gx_kernel<32, 90><<<gxGrid, 256>>>(x, wih1, bih1, gx);
    seq_warp<30><<<BB, 32>>>(gx, whh1, bhh1, bufA);
    // Layer 2: in=30, H=15
    gx_kernel<30, 45><<<gxGrid, 256>>>(bufA, wih2, bih2, gx);
    seq_warp<15><<<BB, 32>>>(gx, whh2, bhh2, bufB);
    // Layer 3: in=15, H=30
    gx_kernel<15, 90><<<gxGrid, 256>>>(bufB, wih3, bih3, gx);
    seq_warp<30><<<BB, 32>>>(gx, whh3, bhh3, bufA);
    // Layer 4: in=30, H=16
    gx_kernel<30, 48><<<gxGrid, 256>>>(bufA, wih4, bih4, gx);
    seq_warp<16><<<BB, 32>>>(gx, whh4, bhh4, bufB);
    // FC + transpose
    dim3 fcGrid(TT / 128, BB);
    fc_kernel<<<fcGrid, 256>>>(bufB, fcw, fcb, out);
}